// round 16
// baseline (speedup 1.0000x reference)
#include <cuda_runtime.h>
#include <cuda_bf16.h>
#include <cstdint>

#define B_   16
#define TQ_  128
#define TK_  256
#define DIN_ 64
#define H_   256
#define DV_  256
#define NEGV (-1000000.0f)

// Scratch (static device arrays: allocation-free). g_kT padded by 8 h-rows so
// the depth-2 prefetch can run past the last row without wrap/guard arithmetic.
__device__ float g_q [B_ * TQ_ * H_];            // [B*Tq, H]
__device__ float g_kT[B_ * H_ * TK_ + 8 * TK_];  // [B, H, Tk] + pad

__device__ __forceinline__ float fast_tanh(float x) {
    float y;
    asm("tanh.approx.f32 %0, %1;" : "=f"(y) : "f"(x));
    return y;
}

// ---------------------------------------------------------------------------
// Kernel 1 (fused projections), 384 blocks x 256 threads.
// ---------------------------------------------------------------------------
__global__ __launch_bounds__(256) void proj_kernel(
    const float* __restrict__ queries, const float* __restrict__ keys,
    const float* __restrict__ wq, const float* __restrict__ wk)
{
    __shared__ __align__(16) float s_buf[16 * 65];
    const int tid = threadIdx.x;
    const int blk = blockIdx.x;

    if (blk < 128) {
        // ---- q projection: rows [row0, row0+16) ----
        const int row0 = blk * 16;
        float w[DIN_];
        #pragma unroll
        for (int d = 0; d < DIN_; d++) w[d] = wq[d * H_ + tid];

        float* s_x = s_buf;                          // [16][64]
        const float* xb = queries + (size_t)row0 * DIN_;
        #pragma unroll
        for (int k = 0; k < 4; k++)
            s_x[tid + k * 256] = xb[tid + k * 256];
        __syncthreads();

        #pragma unroll 4
        for (int r = 0; r < 16; r++) {
            const float4* xr = (const float4*)(s_x + r * DIN_);
            float acc = 0.f;
            #pragma unroll
            for (int d4 = 0; d4 < DIN_ / 4; d4++) {
                float4 xv = xr[d4];
                acc += xv.x * w[d4 * 4 + 0];
                acc += xv.y * w[d4 * 4 + 1];
                acc += xv.z * w[d4 * 4 + 2];
                acc += xv.w * w[d4 * 4 + 3];
            }
            g_q[(size_t)(row0 + r) * H_ + tid] = acc;
        }
    } else {
        // ---- kT projection: batch b, h chunk [h0, h0+16) ----
        const int blk2 = blk - 128;
        const int b  = blk2 >> 4;
        const int h0 = (blk2 & 15) << 4;
        const int t  = tid;

        float x[DIN_];
        const float4* kr = (const float4*)(keys + ((size_t)b * TK_ + t) * DIN_);
        #pragma unroll
        for (int d4 = 0; d4 < DIN_ / 4; d4++) {
            float4 v = kr[d4];
            x[d4 * 4 + 0] = v.x; x[d4 * 4 + 1] = v.y;
            x[d4 * 4 + 2] = v.z; x[d4 * 4 + 3] = v.w;
        }

        float (*s_w)[DIN_ + 1] = (float (*)[DIN_ + 1])s_buf;   // [16][65]
        #pragma unroll
        for (int k = 0; k < 4; k++) {
            int idx = tid + k * 256;
            int hh = idx & 15, d = idx >> 4;
            s_w[hh][d] = wk[d * H_ + h0 + hh];
        }
        __syncthreads();

        float* outb = g_kT + ((size_t)b * H_ + h0) * TK_ + t;
        #pragma unroll 2
        for (int hh = 0; hh < 16; hh++) {
            float acc = 0.f;
            #pragma unroll
            for (int d = 0; d < DIN_; d++) acc += x[d] * s_w[hh][d];
            outb[(size_t)hh * TK_] = acc;
        }
    }
}

// ---------------------------------------------------------------------------
// Kernel 2: fused scores + masked softmax + attn@V.
// CTA = (batch b, 1 query); 2048 CTAs x 512 threads (16 warps).
//   Phase 1 (ADAPTIVE split): nq = live 64-key quarters rounded to pow2
//     {1,2,4}. Warp w -> (kq = w & (nq-1), hseg = w >> lg). Each warp walks
//     only 16*nq h-steps, so small-vl batches get a 4x shorter per-warp
//     critical path AND all 16 warps stay live. Lane owns 2 consecutive keys
//     (coalesced float2 along Tk); register double-buffer prefetch depth 2.
//   Combine+softmax: warp 0 sums the nseg=16/nq h-segment partials, masks.
//   Phase 2: thread (th=tid>>8, v=tid&255); halves interleave over j4 and
//     combine through SMEM.
// ---------------------------------------------------------------------------
__global__ __launch_bounds__(512, 2) void attn_kernel(
    const float* __restrict__ values, const int* __restrict__ valid_lens,
    const float* __restrict__ wv, float* __restrict__ out)
{
    const int b  = blockIdx.x >> 7;          // 128 queries per batch
    const int iq = blockIdx.x & 127;         // query index
    const int tid  = threadIdx.x;
    const int wid  = tid >> 5;
    const int lane = tid & 31;

    __shared__ __align__(16) float s_q[H_];          // 1 KB
    __shared__ __align__(16) float s_wv[H_];         // 1 KB
    __shared__ __align__(16) float s_p[16][TK_];     // 16 KB partials
    __shared__ __align__(16) float s_sc[TK_];        // 1 KB
    __shared__ __align__(16) float s_o[DV_];         // 1 KB phase-2 combine

    const int vl = valid_lens[b];
    if (tid < 256) {
        s_wv[tid] = wv[tid];
        s_q[tid]  = g_q[((size_t)b * TQ_ + iq) * H_ + tid];
    }
    __syncthreads();

    // ---- Phase 1: adaptive (key-quarter x h-segment) partial scores ----
    if (vl > 0) {
        const int nq  = (vl + 63) >> 6;              // live quarters 1..4
        const int lg  = (nq > 2) ? 2 : (nq == 2) ? 1 : 0;
        const int nql = 1 << lg;                     // pow2 quarters 1/2/4
        const int kq   = wid & (nql - 1);
        const int hseg = wid >> lg;
        const int hsteps = 16 << lg;                 // h-steps per warp
        const int h0 = hseg * hsteps;
        const int kl = kq * 32 + lane;               // float2 col in key row
        const bool live = (kq * 64 < vl);            // false only nq==3,kq==3
        float acc0 = 0.f, acc1 = 0.f;

        if (live) {
            constexpr int S = TK_ / 2;               // float2 stride per h
            const float2* kp =
                (const float2*)(g_kT + ((size_t)b * H_ + h0) * TK_) + kl;

            float2 A0 = kp[0 * S], A1 = kp[1 * S], A2 = kp[2 * S], A3 = kp[3 * S];
            float2 Bb0 = kp[4 * S], Bb1 = kp[5 * S], Bb2 = kp[6 * S], Bb3 = kp[7 * S];
            kp += 8 * S;

            const float4* qv4  = (const float4*)s_q  + (h0 >> 2);
            const float4* wvv4 = (const float4*)s_wv + (h0 >> 2);
            const int gmax = hsteps >> 2;            // 4, 8 or 16 groups

            #pragma unroll 2
            for (int g = 0; g < gmax; g += 2) {
                // -- group g: consume A, refill A --
                float4 qv  = qv4[g];
                float4 wvv = wvv4[g];
                acc0 = fmaf(wvv.x, fast_tanh(qv.x + A0.x), acc0);
                acc1 = fmaf(wvv.x, fast_tanh(qv.x + A0.y), acc1);
                acc0 = fmaf(wvv.y, fast_tanh(qv.y + A1.x), acc0);
                acc1 = fmaf(wvv.y, fast_tanh(qv.y + A1.y), acc1);
                acc0 = fmaf(wvv.z, fast_tanh(qv.z + A2.x), acc0);
                acc1 = fmaf(wvv.z, fast_tanh(qv.z + A2.y), acc1);
                acc0 = fmaf(wvv.w, fast_tanh(qv.w + A3.x), acc0);
                acc1 = fmaf(wvv.w, fast_tanh(qv.w + A3.y), acc1);
                A0 = kp[0 * S]; A1 = kp[1 * S]; A2 = kp[2 * S]; A3 = kp[3 * S];

                // -- group g+1: consume B, refill B --
                float4 qw  = qv4[g + 1];
                float4 wvw = wvv4[g + 1];
                acc0 = fmaf(wvw.x, fast_tanh(qw.x + Bb0.x), acc0);
                acc1 = fmaf(wvw.x, fast_tanh(qw.x + Bb0.y), acc1);
                acc0 = fmaf(wvw.y, fast_tanh(qw.y + Bb1.x), acc0);
                acc1 = fmaf(wvw.y, fast_tanh(qw.y + Bb1.y), acc1);
                acc0 = fmaf(wvw.z, fast_tanh(qw.z + Bb2.x), acc0);
                acc1 = fmaf(wvw.z, fast_tanh(qw.z + Bb2.y), acc1);
                acc0 = fmaf(wvw.w, fast_tanh(qw.w + Bb3.x), acc0);
                acc1 = fmaf(wvw.w, fast_tanh(qw.w + Bb3.y), acc1);
                Bb0 = kp[4 * S]; Bb1 = kp[5 * S]; Bb2 = kp[6 * S]; Bb3 = kp[7 * S];
                kp += 8 * S;
            }
        }
        // Every warp stores its (hseg, key-range) partial (zeros if dead).
        ((float2*)s_p[hseg])[kl] = make_float2(acc0, acc1);
    }
    __syncthreads();

    // ---- Combine partials + masked softmax: warp 0 ----
    if (tid < 32) {
        const int l = tid;
        int nseg = 0;
        if (vl > 0) {
            const int nq = (vl + 63) >> 6;
            const int lg = (nq > 2) ? 2 : (nq == 2) ? 1 : 0;
            nseg = 16 >> lg;
        }
        float v[TK_ / 32];
        float m = -3.402823466e38f;
        #pragma unroll
        for (int k = 0; k < TK_ / 32; k++) {
            int j = l + k * 32;
            float p = 0.f;
            for (int s = 0; s < nseg; s++) p += s_p[s][j];
            v[k] = (j < vl) ? p : NEGV;
            m = fmaxf(m, v[k]);
        }
        #pragma unroll
        for (int off = 16; off; off >>= 1)
            m = fmaxf(m, __shfl_xor_sync(0xffffffffu, m, off));
        float sum = 0.f;
        #pragma unroll
        for (int k = 0; k < TK_ / 32; k++) {
            v[k] = __expf(v[k] - m);
            sum += v[k];
        }
        #pragma unroll
        for (int off = 16; off; off >>= 1)
            sum += __shfl_xor_sync(0xffffffffu, sum, off);
        const float inv = 1.0f / sum;
        #pragma unroll
        for (int k = 0; k < TK_ / 32; k++)
            s_sc[l + k * 32] = v[k] * inv;
    }
    __syncthreads();

    // ---- Phase 2: out = attn @ values; th halves interleave over j4 ----
    {
        const int th = tid >> 8;                     // 0 or 1
        const int v  = tid & 255;                    // output column
        const int vl_p2 = (vl == 0) ? TK_ : vl;      // vl==0 -> uniform attn
        const int jmax4 = (vl_p2 + 3) >> 2;

        const float* vbase = values + (size_t)b * TK_ * DV_ + v;
        float oacc = 0.f;

        for (int j4 = th; j4 < jmax4; j4 += 2) {
            float4 a = ((const float4*)s_sc)[j4];
            float v0 = vbase[(j4 * 4 + 0) * DV_];
            float v1 = vbase[(j4 * 4 + 1) * DV_];
            float v2 = vbase[(j4 * 4 + 2) * DV_];
            float v3 = vbase[(j4 * 4 + 3) * DV_];
            oacc += a.x * v0 + a.y * v1 + a.z * v2 + a.w * v3;
        }
        if (th == 1) s_o[v] = oacc;
        __syncthreads();
        if (th == 0)
            out[((size_t)b * TQ_ + iq) * DV_ + v] = oacc + s_o[v];
    }
}

extern "C" void kernel_launch(void* const* d_in, const int* in_sizes, int n_in,
                              void* d_out, int out_size)
{
    const float* queries    = (const float*)d_in[0];
    const float* keys       = (const float*)d_in[1];
    const float* values     = (const float*)d_in[2];
    const int*   valid_lens = (const int*)d_in[3];
    const float* wq         = (const float*)d_in[4];
    const float* wk         = (const float*)d_in[5];
    const float* wv         = (const float*)d_in[6];
    float*       out        = (float*)d_out;

    proj_kernel<<<384, 256>>>(queries, keys, wq, wk);
    attn_kernel<<<B_ * TQ_, 512>>>(values, valid_lens, wv, out);
}

// round 17
// speedup vs baseline: 1.1869x; 1.1869x over previous
#include <cuda_runtime.h>
#include <cuda_bf16.h>
#include <cstdint>

#define B_   16
#define TQ_  128
#define TK_  256
#define DIN_ 64
#define H_   256
#define DV_  256
#define IT_  2           // queries per CTA
#define NEGV (-1000000.0f)

// Scratch (static device arrays: allocation-free). g_kT padded by 8 h-rows so
// the depth-2 prefetch can run past the last row without wrap/guard arithmetic.
__device__ float g_q [B_ * TQ_ * H_];            // [B*Tq, H]
__device__ float g_kT[B_ * H_ * TK_ + 8 * TK_];  // [B, H, Tk] + pad

__device__ __forceinline__ float fast_tanh(float x) {
    float y;
    asm("tanh.approx.f32 %0, %1;" : "=f"(y) : "f"(x));
    return y;
}

// ---------------------------------------------------------------------------
// Kernel 1 (fused projections), 384 blocks x 256 threads.
// ---------------------------------------------------------------------------
__global__ __launch_bounds__(256) void proj_kernel(
    const float* __restrict__ queries, const float* __restrict__ keys,
    const float* __restrict__ wq, const float* __restrict__ wk)
{
    __shared__ __align__(16) float s_buf[16 * 65];
    const int tid = threadIdx.x;
    const int blk = blockIdx.x;

    if (blk < 128) {
        // ---- q projection: rows [row0, row0+16) ----
        const int row0 = blk * 16;
        float w[DIN_];
        #pragma unroll
        for (int d = 0; d < DIN_; d++) w[d] = wq[d * H_ + tid];

        float* s_x = s_buf;                          // [16][64]
        const float* xb = queries + (size_t)row0 * DIN_;
        #pragma unroll
        for (int k = 0; k < 4; k++)
            s_x[tid + k * 256] = xb[tid + k * 256];
        __syncthreads();

        #pragma unroll 4
        for (int r = 0; r < 16; r++) {
            const float4* xr = (const float4*)(s_x + r * DIN_);
            float acc = 0.f;
            #pragma unroll
            for (int d4 = 0; d4 < DIN_ / 4; d4++) {
                float4 xv = xr[d4];
                acc += xv.x * w[d4 * 4 + 0];
                acc += xv.y * w[d4 * 4 + 1];
                acc += xv.z * w[d4 * 4 + 2];
                acc += xv.w * w[d4 * 4 + 3];
            }
            g_q[(size_t)(row0 + r) * H_ + tid] = acc;
        }
    } else {
        // ---- kT projection: batch b, h chunk [h0, h0+16) ----
        const int blk2 = blk - 128;
        const int b  = blk2 >> 4;
        const int h0 = (blk2 & 15) << 4;
        const int t  = tid;

        float x[DIN_];
        const float4* kr = (const float4*)(keys + ((size_t)b * TK_ + t) * DIN_);
        #pragma unroll
        for (int d4 = 0; d4 < DIN_ / 4; d4++) {
            float4 v = kr[d4];
            x[d4 * 4 + 0] = v.x; x[d4 * 4 + 1] = v.y;
            x[d4 * 4 + 2] = v.z; x[d4 * 4 + 3] = v.w;
        }

        float (*s_w)[DIN_ + 1] = (float (*)[DIN_ + 1])s_buf;   // [16][65]
        #pragma unroll
        for (int k = 0; k < 4; k++) {
            int idx = tid + k * 256;
            int hh = idx & 15, d = idx >> 4;
            s_w[hh][d] = wk[d * H_ + h0 + hh];
        }
        __syncthreads();

        float* outb = g_kT + ((size_t)b * H_ + h0) * TK_ + t;
        #pragma unroll 2
        for (int hh = 0; hh < 16; hh++) {
            float acc = 0.f;
            #pragma unroll
            for (int d = 0; d < DIN_; d++) acc += x[d] * s_w[hh][d];
            outb[(size_t)hh * TK_] = acc;
        }
    }
}

// ---------------------------------------------------------------------------
// Kernel 2: fused scores + masked softmax + attn@V.  (R13 champion + p2 split)
// CTA = (batch b, 2-query tile); 1024 CTAs x 512 threads (16 warps).
//   Phase 1: warp w -> (qg = w>>3, kq = (w>>1)&3, hh = w&1): query x 64-key
//     quarter x 128-h half. Lane owns 2 consecutive keys (coalesced float2
//     along Tk). Register double-buffer prefetch depth 2. Fully-masked
//     quarters skip compute and store zero partials.
//   Combine+softmax: warps 0..1, one row each (sums the two h-half partials,
//     applies mask).
//   Phase 2: thread (th=tid>>8, v=tid&255); th halves interleave over j4 and
//     combine through SMEM — all 512 threads participate.
// ---------------------------------------------------------------------------
__global__ __launch_bounds__(512, 2) void attn_kernel(
    const float* __restrict__ values, const int* __restrict__ valid_lens,
    const float* __restrict__ wv, float* __restrict__ out)
{
    const int b  = blockIdx.x >> 6;          // 64 q-tiles per batch
    const int i0 = (blockIdx.x & 63) * IT_;
    const int tid  = threadIdx.x;
    const int wid  = tid >> 5;
    const int lane = tid & 31;
    const int qg = wid >> 3;                 // query within tile (0..1)
    const int kq = (wid >> 1) & 3;           // 64-key quarter
    const int hh = wid & 1;                  // h half (0..1)

    __shared__ __align__(16) float s_q[IT_][H_];        // 2 KB
    __shared__ __align__(16) float s_wv[H_];            // 1 KB
    __shared__ __align__(16) float s_p[IT_][2][TK_];    // 4 KB partials
    __shared__ __align__(16) float s_sc[IT_][TK_];      // 2 KB
    __shared__ __align__(16) float s_o[IT_][DV_];       // 2 KB phase-2 combine

    const int vl = valid_lens[b];
    if (tid < 256) s_wv[tid] = wv[tid];
    if (tid < IT_ * H_)
        s_q[tid >> 8][tid & 255] =
            g_q[((size_t)b * TQ_ + i0 + (tid >> 8)) * H_ + (tid & 255)];
    __syncthreads();

    // ---- Phase 1: partial scores over this warp's 128-h half ----
    const bool live = (kq * 64 < vl);
    const int kl = kq * 32 + lane;           // float2 index within key row
    float acc0 = 0.f, acc1 = 0.f;

    if (live) {
        constexpr int S = TK_ / 2;           // float2 stride per h-step
        const float2* kp =
            (const float2*)(g_kT + ((size_t)b * H_ + hh * (H_ / 2)) * TK_) + kl;

        float2 A0 = kp[0 * S], A1 = kp[1 * S], A2 = kp[2 * S], A3 = kp[3 * S];
        float2 Bb0 = kp[4 * S], Bb1 = kp[5 * S], Bb2 = kp[6 * S], Bb3 = kp[7 * S];
        kp += 8 * S;

        const float4* qv4  = (const float4*)s_q[qg] + hh * (H_ / 8);
        const float4* wvv4 = (const float4*)s_wv    + hh * (H_ / 8);

        #pragma unroll 2
        for (int g = 0; g < H_ / 8; g += 2) {
            // -- group g: consume A, refill A --
            float4 qv  = qv4[g];
            float4 wvv = wvv4[g];
            acc0 = fmaf(wvv.x, fast_tanh(qv.x + A0.x), acc0);
            acc1 = fmaf(wvv.x, fast_tanh(qv.x + A0.y), acc1);
            acc0 = fmaf(wvv.y, fast_tanh(qv.y + A1.x), acc0);
            acc1 = fmaf(wvv.y, fast_tanh(qv.y + A1.y), acc1);
            acc0 = fmaf(wvv.z, fast_tanh(qv.z + A2.x), acc0);
            acc1 = fmaf(wvv.z, fast_tanh(qv.z + A2.y), acc1);
            acc0 = fmaf(wvv.w, fast_tanh(qv.w + A3.x), acc0);
            acc1 = fmaf(wvv.w, fast_tanh(qv.w + A3.y), acc1);
            A0 = kp[0 * S]; A1 = kp[1 * S]; A2 = kp[2 * S]; A3 = kp[3 * S];

            // -- group g+1: consume B, refill B --
            float4 qw  = qv4[g + 1];
            float4 wvw = wvv4[g + 1];
            acc0 = fmaf(wvw.x, fast_tanh(qw.x + Bb0.x), acc0);
            acc1 = fmaf(wvw.x, fast_tanh(qw.x + Bb0.y), acc1);
            acc0 = fmaf(wvw.y, fast_tanh(qw.y + Bb1.x), acc0);
            acc1 = fmaf(wvw.y, fast_tanh(qw.y + Bb1.y), acc1);
            acc0 = fmaf(wvw.z, fast_tanh(qw.z + Bb2.x), acc0);
            acc1 = fmaf(wvw.z, fast_tanh(qw.z + Bb2.y), acc1);
            acc0 = fmaf(wvw.w, fast_tanh(qw.w + Bb3.x), acc0);
            acc1 = fmaf(wvw.w, fast_tanh(qw.w + Bb3.y), acc1);
            Bb0 = kp[4 * S]; Bb1 = kp[5 * S]; Bb2 = kp[6 * S]; Bb3 = kp[7 * S];
            kp += 8 * S;
        }
    }
    // All warps store partials (dead warps contribute zeros).
    ((float2*)s_p[qg][hh])[kl] = make_float2(acc0, acc1);
    __syncthreads();

    // ---- Combine partials + masked softmax: warps 0..1, one row each ----
    if (tid < IT_ * 32) {
        const int i = wid, l = lane;
        float v[TK_ / 32];
        float m = -3.402823466e38f;
        #pragma unroll
        for (int k = 0; k < TK_ / 32; k++) {
            int j = l + k * 32;
            float p = s_p[i][0][j] + s_p[i][1][j];
            v[k] = (j < vl) ? p : NEGV;
            m = fmaxf(m, v[k]);
        }
        #pragma unroll
        for (int off = 16; off; off >>= 1)
            m = fmaxf(m, __shfl_xor_sync(0xffffffffu, m, off));
        float sum = 0.f;
        #pragma unroll
        for (int k = 0; k < TK_ / 32; k++) {
            v[k] = __expf(v[k] - m);
            sum += v[k];
        }
        #pragma unroll
        for (int off = 16; off; off >>= 1)
            sum += __shfl_xor_sync(0xffffffffu, sum, off);
        const float inv = 1.0f / sum;
        #pragma unroll
        for (int k = 0; k < TK_ / 32; k++)
            s_sc[i][l + k * 32] = v[k] * inv;
    }
    __syncthreads();

    // ---- Phase 2: out = attn @ values; th halves interleave over j4 ----
    {
        const int th = tid >> 8;                     // 0 or 1
        const int v  = tid & 255;                    // output column
        const int vl_p2 = (vl == 0) ? TK_ : vl;      // vl==0 -> uniform attn
        const int jmax4 = (vl_p2 + 3) >> 2;

        const float* vbase = values + (size_t)b * TK_ * DV_ + v;
        float oacc[IT_];
        #pragma unroll
        for (int i = 0; i < IT_; i++) oacc[i] = 0.f;

        for (int j4 = th; j4 < jmax4; j4 += 2) {
            float v0 = vbase[(j4 * 4 + 0) * DV_];
            float v1 = vbase[(j4 * 4 + 1) * DV_];
            float v2 = vbase[(j4 * 4 + 2) * DV_];
            float v3 = vbase[(j4 * 4 + 3) * DV_];
            #pragma unroll
            for (int i = 0; i < IT_; i++) {
                float4 a = ((const float4*)s_sc[i])[j4];
                oacc[i] += a.x * v0 + a.y * v1 + a.z * v2 + a.w * v3;
            }
        }
        if (th == 1) {
            #pragma unroll
            for (int i = 0; i < IT_; i++) s_o[i][v] = oacc[i];
        }
        __syncthreads();
        if (th == 0) {
            #pragma unroll
            for (int i = 0; i < IT_; i++)
                out[((size_t)b * TQ_ + i0 + i) * DV_ + v] = oacc[i] + s_o[i][v];
        }
    }
}

extern "C" void kernel_launch(void* const* d_in, const int* in_sizes, int n_in,
                              void* d_out, int out_size)
{
    const float* queries    = (const float*)d_in[0];
    const float* keys       = (const float*)d_in[1];
    const float* values     = (const float*)d_in[2];
    const int*   valid_lens = (const int*)d_in[3];
    const float* wq         = (const float*)d_in[4];
    const float* wk         = (const float*)d_in[5];
    const float* wv         = (const float*)d_in[6];
    float*       out        = (float*)d_out;

    proj_kernel<<<384, 256>>>(queries, keys, wq, wk);
    attn_kernel<<<(B_ * TQ_) / IT_, 512>>>(values, valid_lens, wv, out);
}